// round 5
// baseline (speedup 1.0000x reference)
#include <cuda_runtime.h>
#include <cstdint>

#define BB 2
#define LL 2048
#define DD 1024
#define HH 16
#define DH 64
#define L3 3072

// ---------------- tf32 split + mma helpers ---------------------------------
__device__ __forceinline__ void split_tf32(float x, uint32_t& hi, uint32_t& lo) {
    asm("cvt.rna.tf32.f32 %0, %1;" : "=r"(hi) : "f"(x));
    float r = x - __uint_as_float(hi);
    asm("cvt.rna.tf32.f32 %0, %1;" : "=r"(lo) : "f"(r));
}
__device__ __forceinline__ void split_tf32_f(float x, float& hi, float& lo) {
    uint32_t h, l;
    asm("cvt.rna.tf32.f32 %0, %1;" : "=r"(h) : "f"(x));
    float hf = __uint_as_float(h);
    float r = x - hf;
    asm("cvt.rna.tf32.f32 %0, %1;" : "=r"(l) : "f"(r));
    hi = hf; lo = __uint_as_float(l);
}
__device__ __forceinline__ void mma8(float* c, const uint32_t* a, uint32_t b0, uint32_t b1) {
    asm volatile(
        "mma.sync.aligned.m16n8k8.row.col.f32.tf32.tf32.f32 "
        "{%0,%1,%2,%3}, {%4,%5,%6,%7}, {%8,%9}, {%0,%1,%2,%3};"
        : "+f"(c[0]), "+f"(c[1]), "+f"(c[2]), "+f"(c[3])
        : "r"(a[0]), "r"(a[1]), "r"(a[2]), "r"(a[3]), "r"(b0), "r"(b1));
}
__device__ __forceinline__ uint32_t fu(float x) { return __float_as_uint(x); }

// ---------------- scratch (device globals; no allocations) ----------------
__device__ float g_hi[(size_t)BB * LL * L3];   // tf32-hi of qkv (q pre-scaled)
__device__ float g_lo[(size_t)BB * LL * L3];   // tf32-lo of qkv
__device__ float g_ctx[(size_t)BB * LL * DD];  // context [B*L, D]

// ---------- split-TF32 GEMM: C = A(MxK) @ B(KxN), 64x128x32 tile -----------
// mode 0: write f32 C.  mode 1: write split hi/lo (cols<DD scaled by 0.125).
#define GA_STRIDE 36
#define GB_STRIDE 132
#define SG_SMEM_FLOATS (2 * 64 * GA_STRIDE + 2 * 32 * GB_STRIDE)
#define SG_SMEM_BYTES  (SG_SMEM_FLOATS * 4)

__global__ __launch_bounds__(256, 2) void sgemm_tf32(
    const float* __restrict__ A, const float* __restrict__ B,
    float* __restrict__ C, float* __restrict__ Chi, float* __restrict__ Clo,
    int M, int N, int K, int mode)
{
    extern __shared__ float smg[];
    float* Ahi = smg;                          // [64][36]
    float* Alo = Ahi + 64 * GA_STRIDE;
    float* Bhi = Alo + 64 * GA_STRIDE;         // [32][132]
    float* Blo = Bhi + 32 * GB_STRIDE;

    const int t = threadIdx.x;
    const int w = t >> 5, lane = t & 31;
    const int g = lane >> 2, tg = lane & 3;
    const int wm = w >> 2, wn = w & 3;
    const int bm = blockIdx.y * 64, bn = blockIdx.x * 128;

    float acc[2][4][4];
#pragma unroll
    for (int mi = 0; mi < 2; mi++)
#pragma unroll
        for (int ni = 0; ni < 4; ni++)
#pragma unroll
            for (int e = 0; e < 4; e++) acc[mi][ni][e] = 0.f;

    const int la_row = t >> 3, la_col = (t & 7) * 4;
    const int lb_row = t >> 5, lb_col = (t & 31) * 4;

    float4 pa[2], pb[4];
#pragma unroll
    for (int i = 0; i < 2; i++)
        pa[i] = *(const float4*)(A + (size_t)(bm + la_row + 32 * i) * K + la_col);
#pragma unroll
    for (int i = 0; i < 4; i++)
        pb[i] = *(const float4*)(B + (size_t)(lb_row + 8 * i) * N + bn + lb_col);

    for (int kt = 0; kt < K; kt += 32) {
#pragma unroll
        for (int i = 0; i < 2; i++) {
            int row = la_row + 32 * i;
            float4 h4, l4;
            split_tf32_f(pa[i].x, h4.x, l4.x);
            split_tf32_f(pa[i].y, h4.y, l4.y);
            split_tf32_f(pa[i].z, h4.z, l4.z);
            split_tf32_f(pa[i].w, h4.w, l4.w);
            *(float4*)&Ahi[row * GA_STRIDE + la_col] = h4;
            *(float4*)&Alo[row * GA_STRIDE + la_col] = l4;
        }
#pragma unroll
        for (int i = 0; i < 4; i++) {
            int row = lb_row + 8 * i;
            float4 h4, l4;
            split_tf32_f(pb[i].x, h4.x, l4.x);
            split_tf32_f(pb[i].y, h4.y, l4.y);
            split_tf32_f(pb[i].z, h4.z, l4.z);
            split_tf32_f(pb[i].w, h4.w, l4.w);
            *(float4*)&Bhi[row * GB_STRIDE + lb_col] = h4;
            *(float4*)&Blo[row * GB_STRIDE + lb_col] = l4;
        }
        __syncthreads();

        if (kt + 32 < K) {
#pragma unroll
            for (int i = 0; i < 2; i++)
                pa[i] = *(const float4*)(A + (size_t)(bm + la_row + 32 * i) * K + kt + 32 + la_col);
#pragma unroll
            for (int i = 0; i < 4; i++)
                pb[i] = *(const float4*)(B + (size_t)(kt + 32 + lb_row + 8 * i) * N + bn + lb_col);
        }

#pragma unroll
        for (int ks = 0; ks < 4; ks++) {
            const int k0 = ks * 8;
            uint32_t ah[2][4], al[2][4];
#pragma unroll
            for (int mi = 0; mi < 2; mi++) {
                int rm = wm * 32 + mi * 16;
                ah[mi][0] = fu(Ahi[(rm + g)     * GA_STRIDE + k0 + tg]);
                ah[mi][1] = fu(Ahi[(rm + g + 8) * GA_STRIDE + k0 + tg]);
                ah[mi][2] = fu(Ahi[(rm + g)     * GA_STRIDE + k0 + tg + 4]);
                ah[mi][3] = fu(Ahi[(rm + g + 8) * GA_STRIDE + k0 + tg + 4]);
                al[mi][0] = fu(Alo[(rm + g)     * GA_STRIDE + k0 + tg]);
                al[mi][1] = fu(Alo[(rm + g + 8) * GA_STRIDE + k0 + tg]);
                al[mi][2] = fu(Alo[(rm + g)     * GA_STRIDE + k0 + tg + 4]);
                al[mi][3] = fu(Alo[(rm + g + 8) * GA_STRIDE + k0 + tg + 4]);
            }
#pragma unroll
            for (int ni = 0; ni < 4; ni++) {
                int nb = wn * 32 + ni * 8;
                uint32_t bh0 = fu(Bhi[(k0 + tg)     * GB_STRIDE + nb + g]);
                uint32_t bh1 = fu(Bhi[(k0 + tg + 4) * GB_STRIDE + nb + g]);
                uint32_t bl0 = fu(Blo[(k0 + tg)     * GB_STRIDE + nb + g]);
                uint32_t bl1 = fu(Blo[(k0 + tg + 4) * GB_STRIDE + nb + g]);
#pragma unroll
                for (int mi = 0; mi < 2; mi++) {
                    mma8(acc[mi][ni], ah[mi], bh0, bh1);
                    mma8(acc[mi][ni], ah[mi], bl0, bl1);
                    mma8(acc[mi][ni], al[mi], bh0, bh1);
                }
            }
        }
        __syncthreads();
    }

    const float s = (mode && bn < DD) ? 0.125f : 1.0f;
#pragma unroll
    for (int mi = 0; mi < 2; mi++) {
#pragma unroll
        for (int ni = 0; ni < 4; ni++) {
            int r0 = bm + wm * 32 + mi * 16 + g;
            int c0 = bn + wn * 32 + ni * 8 + 2 * tg;
            size_t o1 = (size_t)r0 * N + c0;
            size_t o2 = (size_t)(r0 + 8) * N + c0;
            if (mode == 0) {
                *(float2*)(C + o1) = make_float2(acc[mi][ni][0], acc[mi][ni][1]);
                *(float2*)(C + o2) = make_float2(acc[mi][ni][2], acc[mi][ni][3]);
            } else {
                float h0, l0, h1, l1, h2, l2, h3, l3;
                split_tf32_f(acc[mi][ni][0] * s, h0, l0);
                split_tf32_f(acc[mi][ni][1] * s, h1, l1);
                split_tf32_f(acc[mi][ni][2] * s, h2, l2);
                split_tf32_f(acc[mi][ni][3] * s, h3, l3);
                *(float2*)(Chi + o1) = make_float2(h0, h1);
                *(float2*)(Clo + o1) = make_float2(l0, l1);
                *(float2*)(Chi + o2) = make_float2(h2, h3);
                *(float2*)(Clo + o2) = make_float2(l2, l3);
            }
        }
    }
}

// ------------- fused attention: QK^T + softmax + align + PV (MMA) ----------
// grid (L/16, H, B), 512 threads (16 warps).
// smem: St[2048][18] + Qh/Ql[16][68] + Kh/Kl[128][68] (K tiles reused for V)
#define ST_S 18
#define QK_S 68
#define ST_FLOATS (2048 * ST_S)
#define ATT_SMEM_FLOATS (ST_FLOATS + 2 * 16 * QK_S + 2 * 128 * QK_S)
#define ATT_SMEM_BYTES  (ATT_SMEM_FLOATS * 4)

__global__ __launch_bounds__(512) void attn_fused_kernel(
    const float* __restrict__ hi, const float* __restrict__ lo,
    const float* __restrict__ bias, float* __restrict__ ctx,
    float* __restrict__ align, int write_align)
{
    extern __shared__ float sm[];
    float* St = sm;                          // [2048][18]
    float* Qh = sm + ST_FLOATS;              // [16][68]
    float* Ql = Qh + 16 * QK_S;
    float* Kh = Ql + 16 * QK_S;              // [128][68]  (also Vh)
    float* Kl = Kh + 128 * QK_S;             //            (also Vl)
    float* Qbuf = Qh;                        // PV reduction buffer (Q dead then)

    const int t = threadIdx.x;
    const int w = t >> 5, lane = t & 31;
    const int g = lane >> 2, tg = lane & 3;
    const int q0 = blockIdx.x * 16;
    const int h  = blockIdx.y;
    const int b  = blockIdx.z;

    const size_t base = (size_t)b * LL * L3 + h * DH;
    const float* qh_g = hi + base;
    const float* ql_g = lo + base;
    const float* kh_g = hi + base + DD;
    const float* kl_g = lo + base + DD;
    const float* vh_g = hi + base + 2 * DD;
    const float* vl_g = lo + base + 2 * DD;

    // ---- Phase A: Q tiles (pre-scaled, pre-split) ----
    {
        int arr = t >> 8;
        int row = (t >> 4) & 15;
        int d4 = (t & 15) * 4;
        const float* src = arr ? ql_g : qh_g;
        float4 v = *(const float4*)(src + (size_t)(q0 + row) * L3 + d4);
        float* dst = arr ? Ql : Qh;
        *(float4*)&dst[row * QK_S + d4] = v;
    }

    // prefetch K chunk 0
    float4 pk[8];
#pragma unroll
    for (int i = 0; i < 4; i++) {
        int idx = i * 512 + t, r = idx >> 4, d4 = (idx & 15) * 4;
        pk[i]     = *(const float4*)(kh_g + (size_t)r * L3 + d4);
    }
#pragma unroll
    for (int i = 0; i < 4; i++) {
        int idx = i * 512 + t, r = idx >> 4, d4 = (idx & 15) * 4;
        pk[4 + i] = *(const float4*)(kl_g + (size_t)r * L3 + d4);
    }
    __syncthreads();

    // Q fragments -> registers (no in-loop splitting)
    uint32_t qah[8][4], qal[8][4];
#pragma unroll
    for (int ks = 0; ks < 8; ks++) {
        int k0 = ks * 8;
        qah[ks][0] = fu(Qh[g * QK_S + k0 + tg]);
        qah[ks][1] = fu(Qh[(g + 8) * QK_S + k0 + tg]);
        qah[ks][2] = fu(Qh[g * QK_S + k0 + tg + 4]);
        qah[ks][3] = fu(Qh[(g + 8) * QK_S + k0 + tg + 4]);
        qal[ks][0] = fu(Ql[g * QK_S + k0 + tg]);
        qal[ks][1] = fu(Ql[(g + 8) * QK_S + k0 + tg]);
        qal[ks][2] = fu(Ql[g * QK_S + k0 + tg + 4]);
        qal[ks][3] = fu(Ql[(g + 8) * QK_S + k0 + tg + 4]);
    }

    // ---- Phase B: QK^T, chunks of 128 keys, warp w -> keys [w*8, w*8+8) ----
    const int nb = w * 8;
    for (int jt = 0; jt < LL; jt += 128) {
#pragma unroll
        for (int i = 0; i < 4; i++) {
            int idx = i * 512 + t, r = idx >> 4, d4 = (idx & 15) * 4;
            *(float4*)&Kh[r * QK_S + d4] = pk[i];
        }
#pragma unroll
        for (int i = 0; i < 4; i++) {
            int idx = i * 512 + t, r = idx >> 4, d4 = (idx & 15) * 4;
            *(float4*)&Kl[r * QK_S + d4] = pk[4 + i];
        }
        __syncthreads();
        if (jt + 128 < LL) {
#pragma unroll
            for (int i = 0; i < 4; i++) {
                int idx = i * 512 + t, r = (idx >> 4) + jt + 128, d4 = (idx & 15) * 4;
                pk[i]     = *(const float4*)(kh_g + (size_t)r * L3 + d4);
            }
#pragma unroll
            for (int i = 0; i < 4; i++) {
                int idx = i * 512 + t, r = (idx >> 4) + jt + 128, d4 = (idx & 15) * 4;
                pk[4 + i] = *(const float4*)(kl_g + (size_t)r * L3 + d4);
            }
        }

        float a0[4] = {0.f, 0.f, 0.f, 0.f}, a1[4] = {0.f, 0.f, 0.f, 0.f};
#pragma unroll
        for (int ks = 0; ks < 8; ks++) {
            int k0 = ks * 8;
            uint32_t bh0 = fu(Kh[(nb + g) * QK_S + k0 + tg]);
            uint32_t bh1 = fu(Kh[(nb + g) * QK_S + k0 + tg + 4]);
            uint32_t bl0 = fu(Kl[(nb + g) * QK_S + k0 + tg]);
            uint32_t bl1 = fu(Kl[(nb + g) * QK_S + k0 + tg + 4]);
            float* acc = (ks & 1) ? a1 : a0;
            mma8(acc, qah[ks], bh0, bh1);
            mma8(acc, qah[ks], bl0, bl1);
            mma8(acc, qal[ks], bh0, bh1);
        }
        int j = jt + nb + 2 * tg;
        St[j * ST_S + g]           = a0[0] + a1[0];
        St[(j + 1) * ST_S + g]     = a0[1] + a1[1];
        St[j * ST_S + g + 8]       = a0[2] + a1[2];
        St[(j + 1) * ST_S + g + 8] = a0[3] + a1[3];
        __syncthreads();
    }

    // prefetch V chunk 0 (overlaps softmax)
    float4 pv[8];
#pragma unroll
    for (int i = 0; i < 4; i++) {
        int idx = i * 512 + t, r = idx >> 4, d4 = (idx & 15) * 4;
        pv[i]     = *(const float4*)(vh_g + (size_t)r * L3 + d4);
    }
#pragma unroll
    for (int i = 0; i < 4; i++) {
        int idx = i * 512 + t, r = idx >> 4, d4 = (idx & 15) * 4;
        pv[4 + i] = *(const float4*)(vl_g + (size_t)r * L3 + d4);
    }

    // ---- Phase C: softmax, one row per warp ----
    {
        const float* brow = bias + (size_t)b * LL;
        const int r = w;
        float m = -1e30f;
        for (int j = lane; j < LL; j += 32) {
            float v = St[j * ST_S + r] + brow[j];
            St[j * ST_S + r] = v;
            m = fmaxf(m, v);
        }
#pragma unroll
        for (int o = 16; o; o >>= 1) m = fmaxf(m, __shfl_xor_sync(0xffffffffu, m, o));
        float s = 0.f;
        for (int j = lane; j < LL; j += 32) {
            float e = __expf(St[j * ST_S + r] - m);
            St[j * ST_S + r] = e;
            s += e;
        }
#pragma unroll
        for (int o = 16; o; o >>= 1) s += __shfl_xor_sync(0xffffffffu, s, o);
        float inv = 1.0f / s;
        for (int j = lane; j < LL; j += 32) St[j * ST_S + r] *= inv;
    }
    __syncthreads();

    // ---- Phase D: align[b,h,j,q0..q0+16) contiguous float2 ----
    if (write_align) {
        float* ap = align + ((size_t)(b * HH + h) * LL) * LL + q0;
#pragma unroll
        for (int k = 0; k < 32; k++) {
            int i = t + k * 512;
            int j = i >> 3;
            int g2 = (i & 7) * 2;
            float2 v = *(const float2*)&St[j * ST_S + g2];
            *(float2*)(ap + (size_t)j * LL + g2) = v;
        }
    }

    // ---- Phase E: PV, warp (nt, kh): n-tile nt, k-half kh ----
    {
        const int nt = w & 7, kh = w >> 3, n0 = nt * 8;
        float eA[4] = {0.f, 0.f, 0.f, 0.f}, eB[4] = {0.f, 0.f, 0.f, 0.f};

        for (int kt = 0; kt < LL; kt += 128) {
            __syncthreads();
#pragma unroll
            for (int i = 0; i < 4; i++) {
                int idx = i * 512 + t, r = idx >> 4, d4 = (idx & 15) * 4;
                *(float4*)&Kh[r * QK_S + d4] = pv[i];
            }
#pragma unroll
            for (int i = 0; i < 4; i++) {
                int idx = i * 512 + t, r = idx >> 4, d4 = (idx & 15) * 4;
                *(float4*)&Kl[r * QK_S + d4] = pv[4 + i];
            }
            __syncthreads();
            if (kt + 128 < LL) {
#pragma unroll
                for (int i = 0; i < 4; i++) {
                    int idx = i * 512 + t, r = (idx >> 4) + kt + 128, d4 = (idx & 15) * 4;
                    pv[i]     = *(const float4*)(vh_g + (size_t)r * L3 + d4);
                }
#pragma unroll
                for (int i = 0; i < 4; i++) {
                    int idx = i * 512 + t, r = (idx >> 4) + kt + 128, d4 = (idx & 15) * 4;
                    pv[4 + i] = *(const float4*)(vl_g + (size_t)r * L3 + d4);
                }
            }

#pragma unroll
            for (int kk = 0; kk < 8; kk++) {
                int lk = (kh * 8 + kk) * 8;
                int kb = kt + lk;
                uint32_t ah[4], al[4];
                split_tf32(St[(kb + tg) * ST_S + g],         ah[0], al[0]);
                split_tf32(St[(kb + tg) * ST_S + g + 8],     ah[1], al[1]);
                split_tf32(St[(kb + tg + 4) * ST_S + g],     ah[2], al[2]);
                split_tf32(St[(kb + tg + 4) * ST_S + g + 8], ah[3], al[3]);
                uint32_t bh0 = fu(Kh[(lk + tg) * QK_S + n0 + g]);
                uint32_t bh1 = fu(Kh[(lk + tg + 4) * QK_S + n0 + g]);
                uint32_t bl0 = fu(Kl[(lk + tg) * QK_S + n0 + g]);
                uint32_t bl1 = fu(Kl[(lk + tg + 4) * QK_S + n0 + g]);
                float* acc = (kk & 1) ? eB : eA;
                mma8(acc, ah, bh0, bh1);
                mma8(acc, ah, bl0, bl1);
                mma8(acc, al, bh0, bh1);
            }
        }

        float e0 = eA[0] + eB[0], e1 = eA[1] + eB[1];
        float e2 = eA[2] + eB[2], e3 = eA[3] + eB[3];
        if (kh == 1)
            *(float4*)&Qbuf[nt * 128 + lane * 4] = make_float4(e0, e1, e2, e3);
        __syncthreads();
        if (kh == 0) {
            float4 p = *(const float4*)&Qbuf[nt * 128 + lane * 4];
            e0 += p.x; e1 += p.y; e2 += p.z; e3 += p.w;
            float* cp = ctx + ((size_t)(b * LL) + q0) * DD + h * DH;
            *(float2*)(cp + (size_t)g * DD + n0 + 2 * tg)       = make_float2(e0, e1);
            *(float2*)(cp + (size_t)(g + 8) * DD + n0 + 2 * tg) = make_float2(e2, e3);
        }
    }
}

// --------------------------------- launch ----------------------------------
extern "C" void kernel_launch(void* const* d_in, const int* in_sizes, int n_in,
                              void* d_out, int out_size)
{
    const float* queries = (const float*)d_in[0];
    const float* bias    = (const float*)d_in[1];
    const float* w_qkv   = (const float*)d_in[2];
    const float* w_o     = (const float*)d_in[3];
    float* out = (float*)d_out;

    const size_t out_elems   = (size_t)BB * LL * DD;
    const size_t align_elems = (size_t)BB * HH * LL * LL;
    int write_align = ((size_t)out_size >= out_elems + align_elems) ? 1 : 0;
    float* align = out + out_elems;

    float *hi_p = nullptr, *lo_p = nullptr, *ctx_p = nullptr;
    cudaGetSymbolAddress((void**)&hi_p,  g_hi);
    cudaGetSymbolAddress((void**)&lo_p,  g_lo);
    cudaGetSymbolAddress((void**)&ctx_p, g_ctx);

    cudaFuncSetAttribute(sgemm_tf32,
                         cudaFuncAttributeMaxDynamicSharedMemorySize, SG_SMEM_BYTES);
    cudaFuncSetAttribute(attn_fused_kernel,
                         cudaFuncAttributeMaxDynamicSharedMemorySize, ATT_SMEM_BYTES);

    // 1) QKV projection -> pre-split hi/lo (q scaled by 0.125 in epilogue)
    {
        dim3 grid(L3 / 128, (BB * LL) / 64);
        sgemm_tf32<<<grid, 256, SG_SMEM_BYTES>>>(
            queries, w_qkv, nullptr, hi_p, lo_p, BB * LL, L3, DD, 1);
    }
    // 2) fused attention
    {
        dim3 grid(LL / 16, HH, BB);
        attn_fused_kernel<<<grid, 512, ATT_SMEM_BYTES>>>(
            hi_p, lo_p, bias, ctx_p, align, write_align);
    }
    // 3) output projection
    {
        dim3 grid(DD / 128, (BB * LL) / 64);
        sgemm_tf32<<<grid, 256, SG_SMEM_BYTES>>>(
            ctx_p, w_o, out, nullptr, nullptr, BB * LL, DD, DD, 0);
    }
}

// round 9
// speedup vs baseline: 1.0407x; 1.0407x over previous
#include <cuda_runtime.h>
#include <cstdint>

#define BB 2
#define LL 2048
#define DD 1024
#define HH 16
#define DH 64
#define L3 3072

// ---------------- tf32 split + mma helpers ---------------------------------
__device__ __forceinline__ void split_tf32_f(float x, float& hi, float& lo) {
    uint32_t h, l;
    asm("cvt.rna.tf32.f32 %0, %1;" : "=r"(h) : "f"(x));
    float hf = __uint_as_float(h);
    float r = x - hf;
    asm("cvt.rna.tf32.f32 %0, %1;" : "=r"(l) : "f"(r));
    hi = hf; lo = __uint_as_float(l);
}
__device__ __forceinline__ float cvt_tf32(float x) {
    uint32_t h;
    asm("cvt.rna.tf32.f32 %0, %1;" : "=r"(h) : "f"(x));
    return __uint_as_float(h);
}
__device__ __forceinline__ void mma8(float* c, const uint32_t* a, uint32_t b0, uint32_t b1) {
    asm volatile(
        "mma.sync.aligned.m16n8k8.row.col.f32.tf32.tf32.f32 "
        "{%0,%1,%2,%3}, {%4,%5,%6,%7}, {%8,%9}, {%0,%1,%2,%3};"
        : "+f"(c[0]), "+f"(c[1]), "+f"(c[2]), "+f"(c[3])
        : "r"(a[0]), "r"(a[1]), "r"(a[2]), "r"(a[3]), "r"(b0), "r"(b1));
}
__device__ __forceinline__ uint32_t fu(float x) { return __float_as_uint(x); }

// split a float4 and store hi/lo float4s to smem
__device__ __forceinline__ void split_store4(float4 v, float* H, float* L) {
    float4 h4, l4;
    split_tf32_f(v.x, h4.x, l4.x);
    split_tf32_f(v.y, h4.y, l4.y);
    split_tf32_f(v.z, h4.z, l4.z);
    split_tf32_f(v.w, h4.w, l4.w);
    *(float4*)H = h4;
    *(float4*)L = l4;
}

// ---------------- scratch (device globals; no allocations) ----------------
__device__ float g_qkv[(size_t)BB * LL * L3];        // [B*L, 3D]
__device__ float g_ctx[(size_t)BB * LL * DD];        // context [B*L, D]

// ---------- split-TF32 GEMM (R4 verbatim, proven): 128x128x32 tile ----------
#define GA_STRIDE 36
#define GB_STRIDE 132
#define SG_SMEM_FLOATS (2 * 128 * GA_STRIDE + 2 * 32 * GB_STRIDE)
#define SG_SMEM_BYTES  (SG_SMEM_FLOATS * 4)

__global__ __launch_bounds__(256) void sgemm_tf32(
    const float* __restrict__ A, const float* __restrict__ B,
    float* __restrict__ C, int M, int N, int K)
{
    extern __shared__ float smg[];
    float* Ahi = smg;                          // [128][36]
    float* Alo = Ahi + 128 * GA_STRIDE;
    float* Bhi = Alo + 128 * GA_STRIDE;        // [32][132]
    float* Blo = Bhi + 32 * GB_STRIDE;

    const int t = threadIdx.x;
    const int w = t >> 5, lane = t & 31;
    const int g = lane >> 2, tg = lane & 3;
    const int wm = w >> 2, wn = w & 3;
    const int bm = blockIdx.y * 128, bn = blockIdx.x * 128;

    float acc[4][4][4];
#pragma unroll
    for (int mi = 0; mi < 4; mi++)
#pragma unroll
        for (int ni = 0; ni < 4; ni++)
#pragma unroll
            for (int e = 0; e < 4; e++) acc[mi][ni][e] = 0.f;

    const int la_row = t >> 3, la_col = (t & 7) * 4;
    const int lb_row = t >> 5, lb_col = (t & 31) * 4;

    float4 pa[4], pb[4];
#pragma unroll
    for (int i = 0; i < 4; i++) {
        pa[i] = *(const float4*)(A + (size_t)(bm + la_row + 32 * i) * K + la_col);
        pb[i] = *(const float4*)(B + (size_t)(lb_row + 8 * i) * N + bn + lb_col);
    }

    for (int kt = 0; kt < K; kt += 32) {
#pragma unroll
        for (int i = 0; i < 4; i++) {
            int row = la_row + 32 * i;
            split_store4(pa[i], &Ahi[row * GA_STRIDE + la_col], &Alo[row * GA_STRIDE + la_col]);
        }
#pragma unroll
        for (int i = 0; i < 4; i++) {
            int row = lb_row + 8 * i;
            split_store4(pb[i], &Bhi[row * GB_STRIDE + lb_col], &Blo[row * GB_STRIDE + lb_col]);
        }
        __syncthreads();

        if (kt + 32 < K) {
#pragma unroll
            for (int i = 0; i < 4; i++) {
                pa[i] = *(const float4*)(A + (size_t)(bm + la_row + 32 * i) * K + kt + 32 + la_col);
                pb[i] = *(const float4*)(B + (size_t)(kt + 32 + lb_row + 8 * i) * N + bn + lb_col);
            }
        }

#pragma unroll
        for (int ks = 0; ks < 4; ks++) {
            const int k0 = ks * 8;
            uint32_t ah[4][4], al[4][4];
#pragma unroll
            for (int mi = 0; mi < 4; mi++) {
                int rm = wm * 64 + mi * 16;
                ah[mi][0] = fu(Ahi[(rm + g)     * GA_STRIDE + k0 + tg]);
                ah[mi][1] = fu(Ahi[(rm + g + 8) * GA_STRIDE + k0 + tg]);
                ah[mi][2] = fu(Ahi[(rm + g)     * GA_STRIDE + k0 + tg + 4]);
                ah[mi][3] = fu(Ahi[(rm + g + 8) * GA_STRIDE + k0 + tg + 4]);
                al[mi][0] = fu(Alo[(rm + g)     * GA_STRIDE + k0 + tg]);
                al[mi][1] = fu(Alo[(rm + g + 8) * GA_STRIDE + k0 + tg]);
                al[mi][2] = fu(Alo[(rm + g)     * GA_STRIDE + k0 + tg + 4]);
                al[mi][3] = fu(Alo[(rm + g + 8) * GA_STRIDE + k0 + tg + 4]);
            }
#pragma unroll
            for (int ni = 0; ni < 4; ni++) {
                int nb = wn * 32 + ni * 8;
                uint32_t bh0 = fu(Bhi[(k0 + tg)     * GB_STRIDE + nb + g]);
                uint32_t bh1 = fu(Bhi[(k0 + tg + 4) * GB_STRIDE + nb + g]);
                uint32_t bl0 = fu(Blo[(k0 + tg)     * GB_STRIDE + nb + g]);
                uint32_t bl1 = fu(Blo[(k0 + tg + 4) * GB_STRIDE + nb + g]);
#pragma unroll
                for (int mi = 0; mi < 4; mi++) {
                    mma8(acc[mi][ni], ah[mi], bh0, bh1);
                    mma8(acc[mi][ni], ah[mi], bl0, bl1);
                    mma8(acc[mi][ni], al[mi], bh0, bh1);
                }
            }
        }
        __syncthreads();
    }

#pragma unroll
    for (int mi = 0; mi < 4; mi++) {
#pragma unroll
        for (int ni = 0; ni < 4; ni++) {
            int r0 = bm + wm * 64 + mi * 16 + g;
            int c0 = bn + wn * 32 + ni * 8 + 2 * tg;
            *(float2*)(C + (size_t)r0 * N + c0)       = make_float2(acc[mi][ni][0], acc[mi][ni][1]);
            *(float2*)(C + (size_t)(r0 + 8) * N + c0) = make_float2(acc[mi][ni][2], acc[mi][ni][3]);
        }
    }
}

// ------------- fused attention (R4 shell + smem pre-split) ------------------
// grid: (L/16, H, B), 256 threads.
// smem: St[2048][18] + Qh/Ql[16][68] + Kh/Kl[128][68] (K arrays reused for V)
#define ST_S 18
#define QK_S 68
#define A_ST  0
#define A_QH  (2048 * ST_S)
#define A_QL  (A_QH + 16 * QK_S)
#define A_KH  (A_QL + 16 * QK_S)
#define A_KL  (A_KH + 128 * QK_S)
#define ATT_SMEM_FLOATS (A_KL + 128 * QK_S)
#define ATT_SMEM_BYTES  (ATT_SMEM_FLOATS * 4)

__global__ __launch_bounds__(256) void attn_fused_kernel(
    const float* __restrict__ qkv, const float* __restrict__ bias,
    float* __restrict__ ctx, float* __restrict__ align, int write_align)
{
    extern __shared__ float sm[];
    float* St = sm + A_ST;           // [2048][18]
    float* Qh = sm + A_QH;           // [16][68]
    float* Ql = sm + A_QL;
    float* Kh = sm + A_KH;           // [128][68]  (also V)
    float* Kl = sm + A_KL;

    const int t = threadIdx.x;
    const int w = t >> 5, lane = t & 31;
    const int g = lane >> 2, tg = lane & 3;
    const int q0 = blockIdx.x * 16;
    const int h  = blockIdx.y;
    const int b  = blockIdx.z;

    const float* kbase = qkv + (size_t)b * LL * L3 + DD + h * DH;
    const float* vbase = qkv + (size_t)b * LL * L3 + 2 * DD + h * DH;

    // ---- Phase A: Q tile, scaled by 0.125, split once into Qh/Ql ----
    {
        int row = t >> 4, d4 = (t & 15) * 4;
        float4 v = *(const float4*)(qkv + (size_t)(b * LL + q0 + row) * L3 + h * DH + d4);
        v.x *= 0.125f; v.y *= 0.125f; v.z *= 0.125f; v.w *= 0.125f;
        split_store4(v, &Qh[row * QK_S + d4], &Ql[row * QK_S + d4]);
    }

    const int lrow = t >> 4;           // 0..15 (+16*i)
    const int ld4  = (t & 15) * 4;

    // ---- Phase B: QK^T via split-tf32 MMA, chunks of 128 keys ----
    float4 pk[8];
#pragma unroll
    for (int i = 0; i < 8; i++)
        pk[i] = *(const float4*)(kbase + (size_t)(lrow + 16 * i) * L3 + ld4);

    for (int jt = 0; jt < LL; jt += 128) {
        __syncthreads();
#pragma unroll
        for (int i = 0; i < 8; i++) {
            int row = lrow + 16 * i;
            split_store4(pk[i], &Kh[row * QK_S + ld4], &Kl[row * QK_S + ld4]);
        }
        __syncthreads();
        if (jt + 128 < LL) {
#pragma unroll
            for (int i = 0; i < 8; i++)
                pk[i] = *(const float4*)(kbase + (size_t)(jt + 128 + lrow + 16 * i) * L3 + ld4);
        }

        float acc2[2][4];
#pragma unroll
        for (int ni = 0; ni < 2; ni++)
#pragma unroll
            for (int e = 0; e < 4; e++) acc2[ni][e] = 0.f;

#pragma unroll
        for (int ks = 0; ks < 8; ks++) {
            const int k0 = ks * 8;
            uint32_t ah[4], al[4];
            ah[0] = fu(Qh[g * QK_S + k0 + tg]);
            ah[1] = fu(Qh[(g + 8) * QK_S + k0 + tg]);
            ah[2] = fu(Qh[g * QK_S + k0 + tg + 4]);
            ah[3] = fu(Qh[(g + 8) * QK_S + k0 + tg + 4]);
            al[0] = fu(Ql[g * QK_S + k0 + tg]);
            al[1] = fu(Ql[(g + 8) * QK_S + k0 + tg]);
            al[2] = fu(Ql[g * QK_S + k0 + tg + 4]);
            al[3] = fu(Ql[(g + 8) * QK_S + k0 + tg + 4]);
#pragma unroll
            for (int ni = 0; ni < 2; ni++) {
                int nb = w * 16 + ni * 8;
                uint32_t bh0 = fu(Kh[(nb + g) * QK_S + k0 + tg]);
                uint32_t bh1 = fu(Kh[(nb + g) * QK_S + k0 + tg + 4]);
                uint32_t bl0 = fu(Kl[(nb + g) * QK_S + k0 + tg]);
                uint32_t bl1 = fu(Kl[(nb + g) * QK_S + k0 + tg + 4]);
                mma8(acc2[ni], ah, bh0, bh1);
                mma8(acc2[ni], ah, bl0, bl1);
                mma8(acc2[ni], al, bh0, bh1);
            }
        }
#pragma unroll
        for (int ni = 0; ni < 2; ni++) {
            int j = jt + w * 16 + ni * 8 + 2 * tg;
            St[j * ST_S + g]           = acc2[ni][0];
            St[(j + 1) * ST_S + g]     = acc2[ni][1];
            St[j * ST_S + g + 8]       = acc2[ni][2];
            St[(j + 1) * ST_S + g + 8] = acc2[ni][3];
        }
        __syncthreads();
    }

    // prefetch first V chunk (overlaps softmax)
    float4 pv[8];
#pragma unroll
    for (int i = 0; i < 8; i++)
        pv[i] = *(const float4*)(vbase + (size_t)(lrow + 16 * i) * L3 + ld4);

    // ---- Phase C: softmax over keys for each of the 16 rows ----
    {
        const float* brow = bias + (size_t)b * LL;
        for (int r = w; r < 16; r += 8) {
            float m = -1e30f;
            for (int j = lane; j < LL; j += 32) {
                float v = St[j * ST_S + r] + brow[j];
                St[j * ST_S + r] = v;
                m = fmaxf(m, v);
            }
#pragma unroll
            for (int o = 16; o; o >>= 1) m = fmaxf(m, __shfl_xor_sync(0xffffffffu, m, o));
            float s = 0.f;
            for (int j = lane; j < LL; j += 32) {
                float e = __expf(St[j * ST_S + r] - m);
                St[j * ST_S + r] = e;
                s += e;
            }
#pragma unroll
            for (int o = 16; o; o >>= 1) s += __shfl_xor_sync(0xffffffffu, s, o);
            float inv = 1.0f / s;
            for (int j = lane; j < LL; j += 32) St[j * ST_S + r] *= inv;
        }
    }
    __syncthreads();

    // ---- Phase D: align[b,h,j,q0..q0+16) — contiguous float2 ----
    if (write_align) {
        float* ap = align + ((size_t)(b * HH + h) * LL) * LL + q0;
#pragma unroll
        for (int k = 0; k < 64; k++) {
            int i = t + k * 256;
            int j = i >> 3;
            int g2 = (i & 7) * 2;
            float2 v = *(const float2*)&St[j * ST_S + g2];
            *(float2*)(ap + (size_t)j * LL + g2) = v;
        }
    }

    // ---- Phase E: PV via MMA (P tf32-hi only; V pre-split 2-term) ----
    {
        const int n0 = w * 8;      // warp's 8 output dims
        float eA[4] = {0.f, 0.f, 0.f, 0.f}, eB[4] = {0.f, 0.f, 0.f, 0.f};

        for (int kt = 0; kt < LL; kt += 128) {
            __syncthreads();
#pragma unroll
            for (int i = 0; i < 8; i++) {
                int row = lrow + 16 * i;
                split_store4(pv[i], &Kh[row * QK_S + ld4], &Kl[row * QK_S + ld4]);
            }
            __syncthreads();
            if (kt + 128 < LL) {
#pragma unroll
                for (int i = 0; i < 8; i++)
                    pv[i] = *(const float4*)(vbase + (size_t)(kt + 128 + lrow + 16 * i) * L3 + ld4);
            }

#pragma unroll
            for (int kk = 0; kk < 16; kk++) {
                const int kb = kt + kk * 8;
                const int lk = kk * 8;
                uint32_t ah[4];
                ah[0] = fu(cvt_tf32(St[(kb + tg) * ST_S + g]));
                ah[1] = fu(cvt_tf32(St[(kb + tg) * ST_S + g + 8]));
                ah[2] = fu(cvt_tf32(St[(kb + tg + 4) * ST_S + g]));
                ah[3] = fu(cvt_tf32(St[(kb + tg + 4) * ST_S + g + 8]));
                uint32_t bh0 = fu(Kh[(lk + tg) * QK_S + n0 + g]);
                uint32_t bh1 = fu(Kh[(lk + tg + 4) * QK_S + n0 + g]);
                uint32_t bl0 = fu(Kl[(lk + tg) * QK_S + n0 + g]);
                uint32_t bl1 = fu(Kl[(lk + tg + 4) * QK_S + n0 + g]);
                mma8(eA, ah, bh0, bh1);
                mma8(eB, ah, bl0, bl1);
            }
        }

        float* cp = ctx + ((size_t)(b * LL) + q0) * DD + h * DH;
        *(float2*)(cp + (size_t)g * DD + n0 + 2 * tg) =
            make_float2(eA[0] + eB[0], eA[1] + eB[1]);
        *(float2*)(cp + (size_t)(g + 8) * DD + n0 + 2 * tg) =
            make_float2(eA[2] + eB[2], eA[3] + eB[3]);
    }
}

// --------------------------------- launch ----------------------------------
extern "C" void kernel_launch(void* const* d_in, const int* in_sizes, int n_in,
                              void* d_out, int out_size)
{
    const float* queries = (const float*)d_in[0];
    const float* bias    = (const float*)d_in[1];
    const float* w_qkv   = (const float*)d_in[2];
    const float* w_o     = (const float*)d_in[3];
    float* out = (float*)d_out;

    const size_t out_elems   = (size_t)BB * LL * DD;
    const size_t align_elems = (size_t)BB * HH * LL * LL;
    int write_align = ((size_t)out_size >= out_elems + align_elems) ? 1 : 0;
    float* align = out + out_elems;

    float *qkv_p = nullptr, *ctx_p = nullptr;
    cudaGetSymbolAddress((void**)&qkv_p, g_qkv);
    cudaGetSymbolAddress((void**)&ctx_p, g_ctx);

    cudaFuncSetAttribute(sgemm_tf32,
                         cudaFuncAttributeMaxDynamicSharedMemorySize, SG_SMEM_BYTES);
    cudaFuncSetAttribute(attn_fused_kernel,
                         cudaFuncAttributeMaxDynamicSharedMemorySize, ATT_SMEM_BYTES);

    // 1) QKV projection: [4096,1024] @ [1024,3072]
    {
        dim3 grid(L3 / 128, (BB * LL) / 128);
        sgemm_tf32<<<grid, 256, SG_SMEM_BYTES>>>(queries, w_qkv, qkv_p, BB * LL, L3, DD);
    }
    // 2) fused attention: QK^T + bias + softmax + align + PV
    {
        dim3 grid(LL / 16, HH, BB);
        attn_fused_kernel<<<grid, 256, ATT_SMEM_BYTES>>>(qkv_p, bias, ctx_p, align, write_align);
    }
    // 3) output projection: [4096,1024] @ [1024,1024]
    {
        dim3 grid(DD / 128, (BB * LL) / 128);
        sgemm_tf32<<<grid, 256, SG_SMEM_BYTES>>>(ctx_p, w_o, out, BB * LL, DD, DD);
    }
}

// round 11
// speedup vs baseline: 1.1869x; 1.1404x over previous
#include <cuda_runtime.h>
#include <cstdint>

#define BB 2
#define LL 2048
#define DD 1024
#define HH 16
#define DH 64
#define L3 3072

// ---------------- tf32 split + mma helpers ---------------------------------
__device__ __forceinline__ void split_tf32(float x, uint32_t& hi, uint32_t& lo) {
    asm("cvt.rna.tf32.f32 %0, %1;" : "=r"(hi) : "f"(x));
    float r = x - __uint_as_float(hi);
    asm("cvt.rna.tf32.f32 %0, %1;" : "=r"(lo) : "f"(r));
}
__device__ __forceinline__ void split_tf32_f(float x, float& hi, float& lo) {
    uint32_t h, l;
    asm("cvt.rna.tf32.f32 %0, %1;" : "=r"(h) : "f"(x));
    float hf = __uint_as_float(h);
    float r = x - hf;
    asm("cvt.rna.tf32.f32 %0, %1;" : "=r"(l) : "f"(r));
    hi = hf; lo = __uint_as_float(l);
}
__device__ __forceinline__ uint32_t cvt_tf32_u(float x) {
    uint32_t h;
    asm("cvt.rna.tf32.f32 %0, %1;" : "=r"(h) : "f"(x));
    return h;
}
__device__ __forceinline__ void mma8(float* c, const uint32_t* a, uint32_t b0, uint32_t b1) {
    asm volatile(
        "mma.sync.aligned.m16n8k8.row.col.f32.tf32.tf32.f32 "
        "{%0,%1,%2,%3}, {%4,%5,%6,%7}, {%8,%9}, {%0,%1,%2,%3};"
        : "+f"(c[0]), "+f"(c[1]), "+f"(c[2]), "+f"(c[3])
        : "r"(a[0]), "r"(a[1]), "r"(a[2]), "r"(a[3]), "r"(b0), "r"(b1));
}
__device__ __forceinline__ uint32_t fu(float x) { return __float_as_uint(x); }

// ---------------- scratch (device globals; no allocations) ----------------
__device__ float g_qkv[(size_t)BB * LL * L3];        // [B*L, 3D]
__device__ float g_ctx[(size_t)BB * LL * DD];        // context [B*L, D]

// ---------- split-TF32 GEMM (R4 verbatim, proven): 128x128x32 tile ----------
#define GA_STRIDE 36
#define GB_STRIDE 132
#define SG_SMEM_FLOATS (2 * 128 * GA_STRIDE + 2 * 32 * GB_STRIDE)
#define SG_SMEM_BYTES  (SG_SMEM_FLOATS * 4)

__global__ __launch_bounds__(256) void sgemm_tf32(
    const float* __restrict__ A, const float* __restrict__ B,
    float* __restrict__ C, int M, int N, int K)
{
    extern __shared__ float smg[];
    float* Ahi = smg;                          // [128][36]
    float* Alo = Ahi + 128 * GA_STRIDE;
    float* Bhi = Alo + 128 * GA_STRIDE;        // [32][132]
    float* Blo = Bhi + 32 * GB_STRIDE;

    const int t = threadIdx.x;
    const int w = t >> 5, lane = t & 31;
    const int g = lane >> 2, tg = lane & 3;
    const int wm = w >> 2, wn = w & 3;
    const int bm = blockIdx.y * 128, bn = blockIdx.x * 128;

    float acc[4][4][4];
#pragma unroll
    for (int mi = 0; mi < 4; mi++)
#pragma unroll
        for (int ni = 0; ni < 4; ni++)
#pragma unroll
            for (int e = 0; e < 4; e++) acc[mi][ni][e] = 0.f;

    const int la_row = t >> 3, la_col = (t & 7) * 4;
    const int lb_row = t >> 5, lb_col = (t & 31) * 4;

    float4 pa[4], pb[4];
#pragma unroll
    for (int i = 0; i < 4; i++) {
        pa[i] = *(const float4*)(A + (size_t)(bm + la_row + 32 * i) * K + la_col);
        pb[i] = *(const float4*)(B + (size_t)(lb_row + 8 * i) * N + bn + lb_col);
    }

    for (int kt = 0; kt < K; kt += 32) {
#pragma unroll
        for (int i = 0; i < 4; i++) {
            int row = la_row + 32 * i;
            float4 h4, l4;
            split_tf32_f(pa[i].x, h4.x, l4.x);
            split_tf32_f(pa[i].y, h4.y, l4.y);
            split_tf32_f(pa[i].z, h4.z, l4.z);
            split_tf32_f(pa[i].w, h4.w, l4.w);
            *(float4*)&Ahi[row * GA_STRIDE + la_col] = h4;
            *(float4*)&Alo[row * GA_STRIDE + la_col] = l4;
        }
#pragma unroll
        for (int i = 0; i < 4; i++) {
            int row = lb_row + 8 * i;
            float4 h4, l4;
            split_tf32_f(pb[i].x, h4.x, l4.x);
            split_tf32_f(pb[i].y, h4.y, l4.y);
            split_tf32_f(pb[i].z, h4.z, l4.z);
            split_tf32_f(pb[i].w, h4.w, l4.w);
            *(float4*)&Bhi[row * GB_STRIDE + lb_col] = h4;
            *(float4*)&Blo[row * GB_STRIDE + lb_col] = l4;
        }
        __syncthreads();

        if (kt + 32 < K) {
#pragma unroll
            for (int i = 0; i < 4; i++) {
                pa[i] = *(const float4*)(A + (size_t)(bm + la_row + 32 * i) * K + kt + 32 + la_col);
                pb[i] = *(const float4*)(B + (size_t)(kt + 32 + lb_row + 8 * i) * N + bn + lb_col);
            }
        }

#pragma unroll
        for (int ks = 0; ks < 4; ks++) {
            const int k0 = ks * 8;
            uint32_t ah[4][4], al[4][4];
#pragma unroll
            for (int mi = 0; mi < 4; mi++) {
                int rm = wm * 64 + mi * 16;
                ah[mi][0] = fu(Ahi[(rm + g)     * GA_STRIDE + k0 + tg]);
                ah[mi][1] = fu(Ahi[(rm + g + 8) * GA_STRIDE + k0 + tg]);
                ah[mi][2] = fu(Ahi[(rm + g)     * GA_STRIDE + k0 + tg + 4]);
                ah[mi][3] = fu(Ahi[(rm + g + 8) * GA_STRIDE + k0 + tg + 4]);
                al[mi][0] = fu(Alo[(rm + g)     * GA_STRIDE + k0 + tg]);
                al[mi][1] = fu(Alo[(rm + g + 8) * GA_STRIDE + k0 + tg]);
                al[mi][2] = fu(Alo[(rm + g)     * GA_STRIDE + k0 + tg + 4]);
                al[mi][3] = fu(Alo[(rm + g + 8) * GA_STRIDE + k0 + tg + 4]);
            }
#pragma unroll
            for (int ni = 0; ni < 4; ni++) {
                int nb = wn * 32 + ni * 8;
                uint32_t bh0 = fu(Bhi[(k0 + tg)     * GB_STRIDE + nb + g]);
                uint32_t bh1 = fu(Bhi[(k0 + tg + 4) * GB_STRIDE + nb + g]);
                uint32_t bl0 = fu(Blo[(k0 + tg)     * GB_STRIDE + nb + g]);
                uint32_t bl1 = fu(Blo[(k0 + tg + 4) * GB_STRIDE + nb + g]);
#pragma unroll
                for (int mi = 0; mi < 4; mi++) {
                    mma8(acc[mi][ni], ah[mi], bh0, bh1);
                    mma8(acc[mi][ni], ah[mi], bl0, bl1);
                    mma8(acc[mi][ni], al[mi], bh0, bh1);
                }
            }
        }
        __syncthreads();
    }

#pragma unroll
    for (int mi = 0; mi < 4; mi++) {
#pragma unroll
        for (int ni = 0; ni < 4; ni++) {
            int r0 = bm + wm * 64 + mi * 16 + g;
            int c0 = bn + wn * 32 + ni * 8 + 2 * tg;
            *(float2*)(C + (size_t)r0 * N + c0)       = make_float2(acc[mi][ni][0], acc[mi][ni][1]);
            *(float2*)(C + (size_t)(r0 + 8) * N + c0) = make_float2(acc[mi][ni][2], acc[mi][ni][3]);
        }
    }
}

// ------------- fused attention (R4 verbatim except Phase E inner loop) ------
// grid: (L/16, H, B), 256 threads.
// smem: St[2048][18] + Qs[16][72] + KVs[128][72]
#define ST_S 18
#define Q_STRIDE  72
#define KV_STRIDE 72
#define ATT_SMEM_FLOATS (2048 * ST_S + 16 * Q_STRIDE + 128 * KV_STRIDE)
#define ATT_SMEM_BYTES  (ATT_SMEM_FLOATS * 4)

__global__ __launch_bounds__(256) void attn_fused_kernel(
    const float* __restrict__ qkv, const float* __restrict__ bias,
    float* __restrict__ ctx, float* __restrict__ align, int write_align)
{
    extern __shared__ float sm[];
    float* St  = sm;                             // [2048][18]
    float* Qs  = sm + 2048 * ST_S;               // [16][72]
    float* KVs = Qs + 16 * Q_STRIDE;             // [128][72]

    const int t = threadIdx.x;
    const int w = t >> 5, lane = t & 31;
    const int g = lane >> 2, tg = lane & 3;
    const int q0 = blockIdx.x * 16;
    const int h  = blockIdx.y;
    const int b  = blockIdx.z;

    const float* kbase = qkv + (size_t)b * LL * L3 + DD + h * DH;
    const float* vbase = qkv + (size_t)b * LL * L3 + 2 * DD + h * DH;

    // ---- Phase A: Q tile, scaled by DH^-0.5 = 0.125 ----
    {
        int row = t >> 4, d4 = (t & 15) * 4;
        float4 v = *(const float4*)(qkv + (size_t)(b * LL + q0 + row) * L3 + h * DH + d4);
        v.x *= 0.125f; v.y *= 0.125f; v.z *= 0.125f; v.w *= 0.125f;
        *(float4*)&Qs[row * Q_STRIDE + d4] = v;
    }

    const int lrow = t >> 4;           // 0..15 (+16*i)
    const int ld4  = (t & 15) * 4;

    // ---- Phase B: QK^T via split-tf32 MMA, chunks of 128 keys ----
    float4 pk[8];
#pragma unroll
    for (int i = 0; i < 8; i++)
        pk[i] = *(const float4*)(kbase + (size_t)(lrow + 16 * i) * L3 + ld4);

    for (int jt = 0; jt < LL; jt += 128) {
        __syncthreads();
#pragma unroll
        for (int i = 0; i < 8; i++)
            *(float4*)&KVs[(lrow + 16 * i) * KV_STRIDE + ld4] = pk[i];
        __syncthreads();
        if (jt + 128 < LL) {
#pragma unroll
            for (int i = 0; i < 8; i++)
                pk[i] = *(const float4*)(kbase + (size_t)(jt + 128 + lrow + 16 * i) * L3 + ld4);
        }

        float acc2[2][4];
#pragma unroll
        for (int ni = 0; ni < 2; ni++)
#pragma unroll
            for (int e = 0; e < 4; e++) acc2[ni][e] = 0.f;

#pragma unroll
        for (int ks = 0; ks < 8; ks++) {
            const int k0 = ks * 8;
            uint32_t ah[4], al[4];
            split_tf32(Qs[g * Q_STRIDE + k0 + tg],           ah[0], al[0]);
            split_tf32(Qs[(g + 8) * Q_STRIDE + k0 + tg],     ah[1], al[1]);
            split_tf32(Qs[g * Q_STRIDE + k0 + tg + 4],       ah[2], al[2]);
            split_tf32(Qs[(g + 8) * Q_STRIDE + k0 + tg + 4], ah[3], al[3]);
#pragma unroll
            for (int ni = 0; ni < 2; ni++) {
                int nb = w * 16 + ni * 8;
                uint32_t bh0, bl0, bh1, bl1;
                split_tf32(KVs[(nb + g) * KV_STRIDE + k0 + tg],     bh0, bl0);
                split_tf32(KVs[(nb + g) * KV_STRIDE + k0 + tg + 4], bh1, bl1);
                mma8(acc2[ni], ah, bh0, bh1);
                mma8(acc2[ni], ah, bl0, bl1);
                mma8(acc2[ni], al, bh0, bh1);
            }
        }
#pragma unroll
        for (int ni = 0; ni < 2; ni++) {
            int j = jt + w * 16 + ni * 8 + 2 * tg;
            St[j * ST_S + g]           = acc2[ni][0];
            St[(j + 1) * ST_S + g]     = acc2[ni][1];
            St[j * ST_S + g + 8]       = acc2[ni][2];
            St[(j + 1) * ST_S + g + 8] = acc2[ni][3];
        }
        __syncthreads();
    }

    // prefetch first V chunk (overlaps softmax)
    float4 pv[8];
#pragma unroll
    for (int i = 0; i < 8; i++)
        pv[i] = *(const float4*)(vbase + (size_t)(lrow + 16 * i) * L3 + ld4);

    // ---- Phase C: softmax over keys for each of the 16 rows ----
    {
        const float* brow = bias + (size_t)b * LL;
        for (int r = w; r < 16; r += 8) {
            float m = -1e30f;
            for (int j = lane; j < LL; j += 32) {
                float v = St[j * ST_S + r] + brow[j];
                St[j * ST_S + r] = v;
                m = fmaxf(m, v);
            }
#pragma unroll
            for (int o = 16; o; o >>= 1) m = fmaxf(m, __shfl_xor_sync(0xffffffffu, m, o));
            float s = 0.f;
            for (int j = lane; j < LL; j += 32) {
                float e = __expf(St[j * ST_S + r] - m);
                St[j * ST_S + r] = e;
                s += e;
            }
#pragma unroll
            for (int o = 16; o; o >>= 1) s += __shfl_xor_sync(0xffffffffu, s, o);
            float inv = 1.0f / s;
            for (int j = lane; j < LL; j += 32) St[j * ST_S + r] *= inv;
        }
    }
    __syncthreads();

    // ---- Phase D: align[b,h,j,q0..q0+16) — contiguous float2 ----
    if (write_align) {
        float* ap = align + ((size_t)(b * HH + h) * LL) * LL + q0;
#pragma unroll
        for (int k = 0; k < 64; k++) {
            int i = t + k * 256;
            int j = i >> 3;
            int g2 = (i & 7) * 2;
            float2 v = *(const float2*)&St[j * ST_S + g2];
            *(float2*)(ap + (size_t)j * LL + g2) = v;
        }
    }

    // ---- Phase E: PV via MMA — P tf32-hi only, 2 independent-acc MMAs ----
    {
        const int n0 = w * 8;      // warp's 8 output dims
        float eA[4] = {0.f, 0.f, 0.f, 0.f};
        float eB[4] = {0.f, 0.f, 0.f, 0.f};

        for (int kt = 0; kt < LL; kt += 128) {
            __syncthreads();
#pragma unroll
            for (int i = 0; i < 8; i++)
                *(float4*)&KVs[(lrow + 16 * i) * KV_STRIDE + ld4] = pv[i];
            __syncthreads();
            if (kt + 128 < LL) {
#pragma unroll
                for (int i = 0; i < 8; i++)
                    pv[i] = *(const float4*)(vbase + (size_t)(kt + 128 + lrow + 16 * i) * L3 + ld4);
            }

#pragma unroll
            for (int kk = 0; kk < 16; kk++) {
                const int kb = kt + kk * 8;
                const int lk = kk * 8;
                uint32_t ah[4];
                ah[0] = cvt_tf32_u(St[(kb + tg) * ST_S + g]);
                ah[1] = cvt_tf32_u(St[(kb + tg) * ST_S + g + 8]);
                ah[2] = cvt_tf32_u(St[(kb + tg + 4) * ST_S + g]);
                ah[3] = cvt_tf32_u(St[(kb + tg + 4) * ST_S + g + 8]);
                uint32_t bh0, bl0, bh1, bl1;
                split_tf32(KVs[(lk + tg) * KV_STRIDE + n0 + g],     bh0, bl0);
                split_tf32(KVs[(lk + tg + 4) * KV_STRIDE + n0 + g], bh1, bl1);
                mma8(eA, ah, bh0, bh1);
                mma8(eB, ah, bl0, bl1);
            }
        }

        float* cp = ctx + ((size_t)(b * LL) + q0) * DD + h * DH;
        *(float2*)(cp + (size_t)g * DD + n0 + 2 * tg) =
            make_float2(eA[0] + eB[0], eA[1] + eB[1]);
        *(float2*)(cp + (size_t)(g + 8) * DD + n0 + 2 * tg) =
            make_float2(eA[2] + eB[2], eA[3] + eB[3]);
    }
}

// --------------------------------- launch ----------------------------------
extern "C" void kernel_launch(void* const* d_in, const int* in_sizes, int n_in,
                              void* d_out, int out_size)
{
    const float* queries = (const float*)d_in[0];
    const float* bias    = (const float*)d_in[1];
    const float* w_qkv   = (const float*)d_in[2];
    const float* w_o     = (const float*)d_in[3];
    float* out = (float*)d_out;

    const size_t out_elems   = (size_t)BB * LL * DD;
    const size_t align_elems = (size_t)BB * HH * LL * LL;
    int write_align = ((size_t)out_size >= out_elems + align_elems) ? 1 : 0;
    float* align = out + out_elems;

    float *qkv_p = nullptr, *ctx_p = nullptr;
    cudaGetSymbolAddress((void**)&qkv_p, g_qkv);
    cudaGetSymbolAddress((void**)&ctx_p, g_ctx);

    cudaFuncSetAttribute(sgemm_tf32,
                         cudaFuncAttributeMaxDynamicSharedMemorySize, SG_SMEM_BYTES);
    cudaFuncSetAttribute(attn_fused_kernel,
                         cudaFuncAttributeMaxDynamicSharedMemorySize, ATT_SMEM_BYTES);

    // 1) QKV projection: [4096,1024] @ [1024,3072]
    {
        dim3 grid(L3 / 128, (BB * LL) / 128);
        sgemm_tf32<<<grid, 256, SG_SMEM_BYTES>>>(queries, w_qkv, qkv_p, BB * LL, L3, DD);
    }
    // 2) fused attention: QK^T + bias + softmax + align + PV
    {
        dim3 grid(LL / 16, HH, BB);
        attn_fused_kernel<<<grid, 256, ATT_SMEM_BYTES>>>(qkv_p, bias, ctx_p, align, write_align);
    }
    // 3) output projection: [4096,1024] @ [1024,1024]
    {
        dim3 grid(DD / 128, (BB * LL) / 128);
        sgemm_tf32<<<grid, 256, SG_SMEM_BYTES>>>(ctx_p, w_o, out, BB * LL, DD, DD);
    }
}